// round 8
// baseline (speedup 1.0000x reference)
#include <cuda_runtime.h>
#include <cuda_bf16.h>
#include <cuda_fp16.h>
#include <mma.h>

using namespace nvcuda;

#define NN 50000
#define NNP 50048              // padded to 391*128 for guard-free GEMM
#define NE 500000
#define NG 512
#define DD 128
#define NO 64
#define NT 11
#define SCAN_BLK 512
#define NCHUNK ((NNP + SCAN_BLK - 1) / SCAN_BLK)   // 98

// ---------------- device scratch ----------------
__device__ float  g_dinv[NNP];       // pads = 0
__device__ int    g_degi[NN];
__device__ int    g_rowstart[NN];
__device__ int    g_cursor[NN];
__device__ int    g_csrc[NE];
__device__ __half g_hw[NNP * DD];    // dinv[row] * (h @ W) in fp16
__device__ float  g_agg[NNP * DD];   // pre-relu layer output; pad rows stay 0
__device__ float  g_t11[NT * DD];    // embed @ W0
__device__ int    g_gstart[NG + 1];
// chained-scan control
__device__ int    g_ticket;
__device__ int    g_flag[NCHUNK];
__device__ int    g_incl[NCHUNK];

__device__ __forceinline__ float4 ld4(const float* p) { return *(const float4*)p; }
__device__ __forceinline__ void st4(float* p, float4 v) { *(float4*)p = v; }

// ---------------- degree count (+ scan-flag reset) ----------------
__global__ void k_deg(const int* __restrict__ dst) {
    int i = blockIdx.x * blockDim.x + threadIdx.x;
    if (i < NCHUNK) g_flag[i] = 0;
    if (i == NCHUNK) g_ticket = 0;
    if (i < NE) atomicAdd(&g_degi[dst[i]], 1);
}

// ---------------- single-pass chained scan (+ dinv, cursor reset fused) ----------------
__global__ void k_scan() {
    __shared__ int sh[SCAN_BLK];
    __shared__ int bid_s, off_s;
    int tid = threadIdx.x;
    if (tid == 0) bid_s = atomicAdd(&g_ticket, 1);
    __syncthreads();
    int c = bid_s;
    int i = c * SCAN_BLK + tid;

    int v = (i < NN) ? g_degi[i] : 0;
    if (i < NNP) g_dinv[i] = (i < NN) ? rsqrtf((float)v + 1.0f) : 0.0f;
    if (i < NN)  g_cursor[i] = 0;

    sh[tid] = v;
    __syncthreads();
    #pragma unroll
    for (int off = 1; off < SCAN_BLK; off <<= 1) {
        int t = (tid >= off) ? sh[tid - off] : 0;
        __syncthreads();
        sh[tid] += t;
        __syncthreads();
    }
    if (tid == 0) {
        int off = 0;
        if (c > 0) {
            while (atomicAdd(&g_flag[c - 1], 0) == 0) { }
            off = g_incl[c - 1];
        }
        g_incl[c] = off + sh[SCAN_BLK - 1];
        __threadfence();
        atomicExch(&g_flag[c], 1);
        off_s = off;
    }
    __syncthreads();
    if (i < NN) g_rowstart[i] = off_s + sh[tid] - v;   // exclusive
}

// ---------------- CSR fill (index only, no weights) ----------------
__global__ void k_fill(const int* __restrict__ src, const int* __restrict__ dst) {
    int e = blockIdx.x * blockDim.x + threadIdx.x;
    if (e >= NE) return;
    int s = src[e], d = dst[e];
    int pos = atomicAdd(&g_cursor[d], 1);
    g_csrc[g_rowstart[d] + pos] = s;
}

// ---------------- t11 = embed @ W0 (11x128) ----------------
__global__ void k_t11(const float* __restrict__ embed, const float* __restrict__ W0) {
    __shared__ float er[DD];
    int r = blockIdx.x;
    int c = threadIdx.x;
    er[c] = embed[r * DD + c];
    __syncthreads();
    float s = 0.f;
    #pragma unroll 8
    for (int k = 0; k < DD; k++) s += er[k] * W0[k * DD + c];
    g_t11[r * DD + c] = s;
}

// ---------------- layer-0: agg = b + dinv[n] * ( dinv[n]*t11[x[n]] + sum_s dinv[s]*t11[x[s]] ) ----------------
__global__ void k_agg0(const float* __restrict__ b, const int* __restrict__ x) {
    __shared__ float st[NT * DD];
    for (int i = threadIdx.x; i < NT * DD; i += 256) st[i] = g_t11[i];
    __syncthreads();

    int n = blockIdx.x * 8 + (threadIdx.x >> 5);
    int lane = threadIdx.x & 31;
    const float4* st4p = (const float4*)st;

    float dn = g_dinv[n];
    float4 hv = st4p[x[n] * 32 + lane];
    float4 acc;
    acc.x = hv.x * dn; acc.y = hv.y * dn;
    acc.z = hv.z * dn; acc.w = hv.w * dn;

    int beg = g_rowstart[n];
    int cnt = g_degi[n];
    int j = 0;
    for (; j + 4 <= cnt; j += 4) {
        int s0 = g_csrc[beg + j],     s1 = g_csrc[beg + j + 1];
        int s2 = g_csrc[beg + j + 2], s3 = g_csrc[beg + j + 3];
        float w0 = g_dinv[s0], w1 = g_dinv[s1];
        float w2 = g_dinv[s2], w3 = g_dinv[s3];
        float4 v0 = st4p[x[s0] * 32 + lane];
        float4 v1 = st4p[x[s1] * 32 + lane];
        float4 v2 = st4p[x[s2] * 32 + lane];
        float4 v3 = st4p[x[s3] * 32 + lane];
        acc.x += v0.x * w0 + v1.x * w1 + v2.x * w2 + v3.x * w3;
        acc.y += v0.y * w0 + v1.y * w1 + v2.y * w2 + v3.y * w3;
        acc.z += v0.z * w0 + v1.z * w1 + v2.z * w2 + v3.z * w3;
        acc.w += v0.w * w0 + v1.w * w1 + v2.w * w2 + v3.w * w3;
    }
    for (; j < cnt; j++) {
        int s0 = g_csrc[beg + j];
        float w0 = g_dinv[s0];
        float4 v0 = st4p[x[s0] * 32 + lane];
        acc.x += v0.x * w0; acc.y += v0.y * w0;
        acc.z += v0.z * w0; acc.w += v0.w * w0;
    }
    float4 bv = ld4(&b[lane * 4]);
    acc.x = bv.x + acc.x * dn;
    acc.y = bv.y + acc.y * dn;
    acc.z = bv.z + acc.z * dn;
    acc.w = bv.w + acc.w * dn;
    st4(&g_agg[n * DD + lane * 4], acc);
}

// ---------------- layers 1,2: agg = b + dinv[n] * ( shw[n] + sum_s shw[s] ), shw pre-scaled fp16 ----------------
__device__ __forceinline__ void h4add(uint2 h, float4& acc) {
    float2 f01 = __half22float2(*(__half2*)&h.x);
    float2 f23 = __half22float2(*(__half2*)&h.y);
    acc.x += f01.x; acc.y += f01.y;
    acc.z += f23.x; acc.w += f23.y;
}

__global__ void k_agg(const float* __restrict__ b) {
    int n = blockIdx.x * 8 + (threadIdx.x >> 5);
    int lane = threadIdx.x & 31;
    const uint2* hw8 = (const uint2*)g_hw;    // 4 halves per uint2; row = 32 uint2

    float dn = g_dinv[n];
    float4 acc = make_float4(0.f, 0.f, 0.f, 0.f);
    h4add(hw8[n * 32 + lane], acc);           // self term (pre-scaled)

    int beg = g_rowstart[n];
    int cnt = g_degi[n];
    int j = 0;
    for (; j + 8 <= cnt; j += 8) {
        int s0 = g_csrc[beg + j],     s1 = g_csrc[beg + j + 1];
        int s2 = g_csrc[beg + j + 2], s3 = g_csrc[beg + j + 3];
        int s4 = g_csrc[beg + j + 4], s5 = g_csrc[beg + j + 5];
        int s6 = g_csrc[beg + j + 6], s7 = g_csrc[beg + j + 7];
        uint2 v0 = hw8[s0 * 32 + lane];
        uint2 v1 = hw8[s1 * 32 + lane];
        uint2 v2 = hw8[s2 * 32 + lane];
        uint2 v3 = hw8[s3 * 32 + lane];
        uint2 v4 = hw8[s4 * 32 + lane];
        uint2 v5 = hw8[s5 * 32 + lane];
        uint2 v6 = hw8[s6 * 32 + lane];
        uint2 v7 = hw8[s7 * 32 + lane];
        h4add(v0, acc); h4add(v1, acc); h4add(v2, acc); h4add(v3, acc);
        h4add(v4, acc); h4add(v5, acc); h4add(v6, acc); h4add(v7, acc);
    }
    for (; j < cnt; j++) {
        h4add(hw8[g_csrc[beg + j] * 32 + lane], acc);
    }
    float4 bv = ld4(&b[lane * 4]);
    acc.x = bv.x + acc.x * dn;
    acc.y = bv.y + acc.y * dn;
    acc.z = bv.z + acc.z * dn;
    acc.w = bv.w + acc.w * dn;
    st4(&g_agg[n * DD + lane * 4], acc);
}

// ---------------- tf32 GEMM: hw = fp16( dinv[row] * (relu(agg) @ W) ) ----------------
#define APAD 40     // A smem row stride (floats)
#define BPAD 136    // B smem row stride (floats)
__global__ __launch_bounds__(256) void k_gemm(const float* __restrict__ W) {
    __shared__ float As[128 * APAD];
    __shared__ float Bs[32 * BPAD];
    int m0 = blockIdx.x * 128;
    int tid = threadIdx.x;
    int wid = tid >> 5;
    int lane = tid & 31;
    int warp_m = wid >> 1;        // 0..3
    int warp_n = wid & 1;         // 0..1

    wmma::fragment<wmma::accumulator, 16, 16, 8, float> c[2][4];
    #pragma unroll
    for (int i = 0; i < 2; i++)
        #pragma unroll
        for (int j = 0; j < 4; j++) wmma::fill_fragment(c[i][j], 0.0f);

    for (int k0 = 0; k0 < DD; k0 += 32) {
        #pragma unroll
        for (int t = 0; t < 4; t++) {
            int f = tid + t * 256;
            int row = f >> 3, c4 = (f & 7) * 4;
            float4 v = ld4(&g_agg[(m0 + row) * DD + k0 + c4]);
            float* d = &As[row * APAD + c4];
            d[0] = wmma::__float_to_tf32(fmaxf(v.x, 0.f));
            d[1] = wmma::__float_to_tf32(fmaxf(v.y, 0.f));
            d[2] = wmma::__float_to_tf32(fmaxf(v.z, 0.f));
            d[3] = wmma::__float_to_tf32(fmaxf(v.w, 0.f));
        }
        #pragma unroll
        for (int t = 0; t < 4; t++) {
            int f = tid + t * 256;
            int row = f >> 5, c4 = (f & 31) * 4;
            float4 v = ld4(&W[(k0 + row) * DD + c4]);
            float* d = &Bs[row * BPAD + c4];
            d[0] = wmma::__float_to_tf32(v.x);
            d[1] = wmma::__float_to_tf32(v.y);
            d[2] = wmma::__float_to_tf32(v.z);
            d[3] = wmma::__float_to_tf32(v.w);
        }
        __syncthreads();
        #pragma unroll
        for (int kk = 0; kk < 4; kk++) {
            wmma::fragment<wmma::matrix_a, 16, 16, 8, wmma::precision::tf32, wmma::row_major> a[2];
            wmma::fragment<wmma::matrix_b, 16, 16, 8, wmma::precision::tf32, wmma::row_major> bfr[4];
            #pragma unroll
            for (int i = 0; i < 2; i++)
                wmma::load_matrix_sync(a[i], &As[(warp_m * 32 + i * 16) * APAD + kk * 8], APAD);
            #pragma unroll
            for (int j = 0; j < 4; j++)
                wmma::load_matrix_sync(bfr[j], &Bs[(kk * 8) * BPAD + warp_n * 64 + j * 16], BPAD);
            #pragma unroll
            for (int i = 0; i < 2; i++)
                #pragma unroll
                for (int j = 0; j < 4; j++)
                    wmma::mma_sync(c[i][j], a[i], bfr[j], c[i][j]);
        }
        __syncthreads();
    }

    // epilogue: stage frags in smem, scale by dinv[row], convert fp16, 16B stores
    float* stg = &As[wid * 272];            // 272 floats per warp, 16B aligned
    int srow = lane >> 1;
    int scol = (lane & 1) * 8;
    #pragma unroll
    for (int i = 0; i < 2; i++) {
        #pragma unroll
        for (int j = 0; j < 4; j++) {
            wmma::store_matrix_sync(stg, c[i][j], 16, wmma::mem_row_major);
            __syncwarp();
            int grow = m0 + warp_m * 32 + i * 16 + srow;
            float dv = g_dinv[grow];
            float4 f0 = *(float4*)&stg[srow * 16 + scol];
            float4 f1 = *(float4*)&stg[srow * 16 + scol + 4];
            __half2 p0 = __floats2half2_rn(f0.x * dv, f0.y * dv);
            __half2 p1 = __floats2half2_rn(f0.z * dv, f0.w * dv);
            __half2 p2 = __floats2half2_rn(f1.x * dv, f1.y * dv);
            __half2 p3 = __floats2half2_rn(f1.z * dv, f1.w * dv);
            uint4 pk = make_uint4(*(unsigned*)&p0, *(unsigned*)&p1,
                                  *(unsigned*)&p2, *(unsigned*)&p3);
            *(uint4*)&g_hw[grow * DD + warp_n * 64 + j * 16 + scol] = pk;
            __syncwarp();
        }
    }
}

// ---------------- graph boundaries from sorted batch ----------------
__global__ void k_bound(const int* __restrict__ batch) {
    int i = blockIdx.x * blockDim.x + threadIdx.x;
    if (i >= NN) return;
    int b = batch[i];
    int prev = (i == 0) ? -1 : batch[i - 1];
    for (int g = prev + 1; g <= b; g++) g_gstart[g] = i;
    if (i == NN - 1)
        for (int g = b + 1; g <= NG; g++) g_gstart[g] = NN;
}

// ---------------- fused mean-pool + FC ----------------
__global__ void k_poolfc(const float* __restrict__ fc_w, const float* __restrict__ fc_b,
                         float* __restrict__ out) {
    __shared__ float pm[DD];
    int g = blockIdx.x;
    int d = threadIdx.x;
    int s = g_gstart[g], e = g_gstart[g + 1];
    float acc = 0.f;
    for (int n = s; n < e; n++) acc += fmaxf(g_agg[n * DD + d], 0.f);
    float inv = 1.0f / fmaxf((float)(e - s), 1.0f);
    pm[d] = acc * inv;
    __syncthreads();
    if (d < NO) {
        float sum = fc_b[d];
        #pragma unroll 8
        for (int k = 0; k < DD; k++) sum += pm[k] * fc_w[k * NO + d];
        out[g * NO + d] = sum;
    }
}

// ---------------- launch ----------------
extern "C" void kernel_launch(void* const* d_in, const int* in_sizes, int n_in,
                              void* d_out, int out_size) {
    const int*   x     = (const int*)d_in[0];
    const int*   eidx  = (const int*)d_in[1];
    const int*   batch = (const int*)d_in[2];
    const float* embed = (const float*)d_in[3];
    const float* W0    = (const float*)d_in[4];
    const float* b0    = (const float*)d_in[5];
    const float* W1    = (const float*)d_in[6];
    const float* b1    = (const float*)d_in[7];
    const float* W2    = (const float*)d_in[8];
    const float* b2    = (const float*)d_in[9];
    const float* fc_w  = (const float*)d_in[10];
    const float* fc_b  = (const float*)d_in[11];
    float* out = (float*)d_out;

    const int* src = eidx;
    const int* dst = eidx + NE;

    void* p_degi;
    cudaGetSymbolAddress(&p_degi, g_degi);
    cudaMemsetAsync(p_degi, 0, NN * sizeof(int));

    // graph structure
    k_deg<<<(NE + 255) / 256, 256>>>(dst);
    k_scan<<<NCHUNK, SCAN_BLK>>>();
    k_fill<<<(NE + 255) / 256, 256>>>(src, dst);
    k_bound<<<(NN + 255) / 256, 256>>>(batch);

    // layer 0: embed-gather fused into aggregation
    k_t11<<<NT, DD>>>(embed, W0);
    k_agg0<<<NN / 8, 256>>>(b0, x);

    // layer 1
    k_gemm<<<NNP / 128, 256>>>(W1);
    k_agg<<<NN / 8, 256>>>(b1);

    // layer 2
    k_gemm<<<NNP / 128, 256>>>(W2);
    k_agg<<<NN / 8, 256>>>(b2);

    // pool + fc
    k_poolfc<<<NG, DD>>>(fc_w, fc_b, out);
}

// round 9
// speedup vs baseline: 1.0001x; 1.0001x over previous
#include <cuda_runtime.h>
#include <cuda_bf16.h>
#include <cuda_fp16.h>
#include <mma.h>

using namespace nvcuda;

#define NN 50000
#define NNP 50048              // padded to 391*128 for guard-free GEMM
#define NE 500000
#define NG 512
#define DD 128
#define NO 64
#define NT 11
#define SCAN_BLK 512
#define NCHUNK ((NNP + SCAN_BLK - 1) / SCAN_BLK)   // 98

// ---------------- device scratch ----------------
__device__ float  g_dinv[NNP];       // pads = 0
__device__ int    g_degi[NN];
__device__ int    g_rowstart[NN];
__device__ int    g_cursor[NN];
__device__ int    g_csrc[NE];
__device__ __half g_hw[NNP * DD];    // dinv[row] * (h @ W) in fp16
__device__ float  g_agg[NNP * DD];   // pre-relu layer output; pad rows stay 0
__device__ float  g_t11[NT * DD];    // embed @ W0
__device__ int    g_gstart[NG + 1];
// chained-scan control
__device__ int    g_ticket;
__device__ int    g_flag[NCHUNK];
__device__ int    g_incl[NCHUNK];

__device__ __forceinline__ float4 ld4(const float* p) { return *(const float4*)p; }
__device__ __forceinline__ void st4(float* p, float4 v) { *(float4*)p = v; }

// ---------------- degree count (+ scan-flag reset) ----------------
__global__ void k_deg(const int* __restrict__ dst) {
    int i = blockIdx.x * blockDim.x + threadIdx.x;
    if (i < NCHUNK) g_flag[i] = 0;
    if (i == NCHUNK) g_ticket = 0;
    if (i < NE) atomicAdd(&g_degi[dst[i]], 1);
}

// ---------------- single-pass chained scan (+ dinv, cursor reset fused) ----------------
__global__ void k_scan() {
    __shared__ int sh[SCAN_BLK];
    __shared__ int bid_s, off_s;
    int tid = threadIdx.x;
    if (tid == 0) bid_s = atomicAdd(&g_ticket, 1);
    __syncthreads();
    int c = bid_s;
    int i = c * SCAN_BLK + tid;

    int v = (i < NN) ? g_degi[i] : 0;
    if (i < NNP) g_dinv[i] = (i < NN) ? rsqrtf((float)v + 1.0f) : 0.0f;
    if (i < NN)  g_cursor[i] = 0;

    sh[tid] = v;
    __syncthreads();
    #pragma unroll
    for (int off = 1; off < SCAN_BLK; off <<= 1) {
        int t = (tid >= off) ? sh[tid - off] : 0;
        __syncthreads();
        sh[tid] += t;
        __syncthreads();
    }
    if (tid == 0) {
        int off = 0;
        if (c > 0) {
            while (atomicAdd(&g_flag[c - 1], 0) == 0) { }
            off = g_incl[c - 1];
        }
        g_incl[c] = off + sh[SCAN_BLK - 1];
        __threadfence();
        atomicExch(&g_flag[c], 1);
        off_s = off;
    }
    __syncthreads();
    if (i < NN) g_rowstart[i] = off_s + sh[tid] - v;   // exclusive
}

// ---------------- CSR fill (index only, no weights) ----------------
__global__ void k_fill(const int* __restrict__ src, const int* __restrict__ dst) {
    int e = blockIdx.x * blockDim.x + threadIdx.x;
    if (e >= NE) return;
    int s = src[e], d = dst[e];
    int pos = atomicAdd(&g_cursor[d], 1);
    g_csrc[g_rowstart[d] + pos] = s;
}

// ---------------- t11 = embed @ W0 (11x128) ----------------
__global__ void k_t11(const float* __restrict__ embed, const float* __restrict__ W0) {
    __shared__ float er[DD];
    int r = blockIdx.x;
    int c = threadIdx.x;
    er[c] = embed[r * DD + c];
    __syncthreads();
    float s = 0.f;
    #pragma unroll 8
    for (int k = 0; k < DD; k++) s += er[k] * W0[k * DD + c];
    g_t11[r * DD + c] = s;
}

// ---------------- layer-0: agg = b + dinv[n] * ( dinv[n]*t11[x[n]] + sum_s dinv[s]*t11[x[s]] ) ----------------
__global__ void k_agg0(const float* __restrict__ b, const int* __restrict__ x) {
    __shared__ float st[NT * DD];
    for (int i = threadIdx.x; i < NT * DD; i += 256) st[i] = g_t11[i];
    __syncthreads();

    int n = blockIdx.x * 8 + (threadIdx.x >> 5);
    int lane = threadIdx.x & 31;
    const float4* st4p = (const float4*)st;

    float dn = g_dinv[n];
    float4 hv = st4p[x[n] * 32 + lane];
    float4 acc;
    acc.x = hv.x * dn; acc.y = hv.y * dn;
    acc.z = hv.z * dn; acc.w = hv.w * dn;

    int beg = g_rowstart[n];
    int cnt = g_degi[n];
    int j = 0;
    for (; j + 4 <= cnt; j += 4) {
        int s0 = g_csrc[beg + j],     s1 = g_csrc[beg + j + 1];
        int s2 = g_csrc[beg + j + 2], s3 = g_csrc[beg + j + 3];
        float w0 = g_dinv[s0], w1 = g_dinv[s1];
        float w2 = g_dinv[s2], w3 = g_dinv[s3];
        float4 v0 = st4p[x[s0] * 32 + lane];
        float4 v1 = st4p[x[s1] * 32 + lane];
        float4 v2 = st4p[x[s2] * 32 + lane];
        float4 v3 = st4p[x[s3] * 32 + lane];
        acc.x += v0.x * w0 + v1.x * w1 + v2.x * w2 + v3.x * w3;
        acc.y += v0.y * w0 + v1.y * w1 + v2.y * w2 + v3.y * w3;
        acc.z += v0.z * w0 + v1.z * w1 + v2.z * w2 + v3.z * w3;
        acc.w += v0.w * w0 + v1.w * w1 + v2.w * w2 + v3.w * w3;
    }
    for (; j < cnt; j++) {
        int s0 = g_csrc[beg + j];
        float w0 = g_dinv[s0];
        float4 v0 = st4p[x[s0] * 32 + lane];
        acc.x += v0.x * w0; acc.y += v0.y * w0;
        acc.z += v0.z * w0; acc.w += v0.w * w0;
    }
    float4 bv = ld4(&b[lane * 4]);
    acc.x = bv.x + acc.x * dn;
    acc.y = bv.y + acc.y * dn;
    acc.z = bv.z + acc.z * dn;
    acc.w = bv.w + acc.w * dn;
    st4(&g_agg[n * DD + lane * 4], acc);
}

// ---------------- layers 1,2: agg = b + dinv[n] * ( shw[n] + sum_s shw[s] ), shw pre-scaled fp16 ----------------
__device__ __forceinline__ void h4add(uint2 h, float4& acc) {
    float2 f01 = __half22float2(*(__half2*)&h.x);
    float2 f23 = __half22float2(*(__half2*)&h.y);
    acc.x += f01.x; acc.y += f01.y;
    acc.z += f23.x; acc.w += f23.y;
}

__global__ void k_agg(const float* __restrict__ b) {
    int n = blockIdx.x * 8 + (threadIdx.x >> 5);
    int lane = threadIdx.x & 31;
    const uint2* hw8 = (const uint2*)g_hw;    // 4 halves per uint2; row = 32 uint2

    float dn = g_dinv[n];
    float4 acc = make_float4(0.f, 0.f, 0.f, 0.f);
    h4add(hw8[n * 32 + lane], acc);           // self term (pre-scaled)

    int beg = g_rowstart[n];
    int cnt = g_degi[n];
    int j = 0;
    for (; j + 8 <= cnt; j += 8) {
        int s0 = g_csrc[beg + j],     s1 = g_csrc[beg + j + 1];
        int s2 = g_csrc[beg + j + 2], s3 = g_csrc[beg + j + 3];
        int s4 = g_csrc[beg + j + 4], s5 = g_csrc[beg + j + 5];
        int s6 = g_csrc[beg + j + 6], s7 = g_csrc[beg + j + 7];
        uint2 v0 = hw8[s0 * 32 + lane];
        uint2 v1 = hw8[s1 * 32 + lane];
        uint2 v2 = hw8[s2 * 32 + lane];
        uint2 v3 = hw8[s3 * 32 + lane];
        uint2 v4 = hw8[s4 * 32 + lane];
        uint2 v5 = hw8[s5 * 32 + lane];
        uint2 v6 = hw8[s6 * 32 + lane];
        uint2 v7 = hw8[s7 * 32 + lane];
        h4add(v0, acc); h4add(v1, acc); h4add(v2, acc); h4add(v3, acc);
        h4add(v4, acc); h4add(v5, acc); h4add(v6, acc); h4add(v7, acc);
    }
    for (; j < cnt; j++) {
        h4add(hw8[g_csrc[beg + j] * 32 + lane], acc);
    }
    float4 bv = ld4(&b[lane * 4]);
    acc.x = bv.x + acc.x * dn;
    acc.y = bv.y + acc.y * dn;
    acc.z = bv.z + acc.z * dn;
    acc.w = bv.w + acc.w * dn;
    st4(&g_agg[n * DD + lane * 4], acc);
}

// ---------------- tf32 GEMM: hw = fp16( dinv[row] * (relu(agg) @ W) ) ----------------
#define APAD 40     // A smem row stride (floats)
#define BPAD 136    // B smem row stride (floats)
__global__ __launch_bounds__(256) void k_gemm(const float* __restrict__ W) {
    __shared__ float As[128 * APAD];
    __shared__ float Bs[32 * BPAD];
    int m0 = blockIdx.x * 128;
    int tid = threadIdx.x;
    int wid = tid >> 5;
    int lane = tid & 31;
    int warp_m = wid >> 1;        // 0..3
    int warp_n = wid & 1;         // 0..1

    wmma::fragment<wmma::accumulator, 16, 16, 8, float> c[2][4];
    #pragma unroll
    for (int i = 0; i < 2; i++)
        #pragma unroll
        for (int j = 0; j < 4; j++) wmma::fill_fragment(c[i][j], 0.0f);

    for (int k0 = 0; k0 < DD; k0 += 32) {
        #pragma unroll
        for (int t = 0; t < 4; t++) {
            int f = tid + t * 256;
            int row = f >> 3, c4 = (f & 7) * 4;
            float4 v = ld4(&g_agg[(m0 + row) * DD + k0 + c4]);
            float* d = &As[row * APAD + c4];
            d[0] = wmma::__float_to_tf32(fmaxf(v.x, 0.f));
            d[1] = wmma::__float_to_tf32(fmaxf(v.y, 0.f));
            d[2] = wmma::__float_to_tf32(fmaxf(v.z, 0.f));
            d[3] = wmma::__float_to_tf32(fmaxf(v.w, 0.f));
        }
        #pragma unroll
        for (int t = 0; t < 4; t++) {
            int f = tid + t * 256;
            int row = f >> 5, c4 = (f & 31) * 4;
            float4 v = ld4(&W[(k0 + row) * DD + c4]);
            float* d = &Bs[row * BPAD + c4];
            d[0] = wmma::__float_to_tf32(v.x);
            d[1] = wmma::__float_to_tf32(v.y);
            d[2] = wmma::__float_to_tf32(v.z);
            d[3] = wmma::__float_to_tf32(v.w);
        }
        __syncthreads();
        #pragma unroll
        for (int kk = 0; kk < 4; kk++) {
            wmma::fragment<wmma::matrix_a, 16, 16, 8, wmma::precision::tf32, wmma::row_major> a[2];
            wmma::fragment<wmma::matrix_b, 16, 16, 8, wmma::precision::tf32, wmma::row_major> bfr[4];
            #pragma unroll
            for (int i = 0; i < 2; i++)
                wmma::load_matrix_sync(a[i], &As[(warp_m * 32 + i * 16) * APAD + kk * 8], APAD);
            #pragma unroll
            for (int j = 0; j < 4; j++)
                wmma::load_matrix_sync(bfr[j], &Bs[(kk * 8) * BPAD + warp_n * 64 + j * 16], BPAD);
            #pragma unroll
            for (int i = 0; i < 2; i++)
                #pragma unroll
                for (int j = 0; j < 4; j++)
                    wmma::mma_sync(c[i][j], a[i], bfr[j], c[i][j]);
        }
        __syncthreads();
    }

    // epilogue: stage frags in smem, scale by dinv[row], convert fp16, 16B stores
    float* stg = &As[wid * 272];            // 272 floats per warp, 16B aligned
    int srow = lane >> 1;
    int scol = (lane & 1) * 8;
    #pragma unroll
    for (int i = 0; i < 2; i++) {
        #pragma unroll
        for (int j = 0; j < 4; j++) {
            wmma::store_matrix_sync(stg, c[i][j], 16, wmma::mem_row_major);
            __syncwarp();
            int grow = m0 + warp_m * 32 + i * 16 + srow;
            float dv = g_dinv[grow];
            float4 f0 = *(float4*)&stg[srow * 16 + scol];
            float4 f1 = *(float4*)&stg[srow * 16 + scol + 4];
            __half2 p0 = __floats2half2_rn(f0.x * dv, f0.y * dv);
            __half2 p1 = __floats2half2_rn(f0.z * dv, f0.w * dv);
            __half2 p2 = __floats2half2_rn(f1.x * dv, f1.y * dv);
            __half2 p3 = __floats2half2_rn(f1.z * dv, f1.w * dv);
            uint4 pk = make_uint4(*(unsigned*)&p0, *(unsigned*)&p1,
                                  *(unsigned*)&p2, *(unsigned*)&p3);
            *(uint4*)&g_hw[grow * DD + warp_n * 64 + j * 16 + scol] = pk;
            __syncwarp();
        }
    }
}

// ---------------- graph boundaries from sorted batch ----------------
__global__ void k_bound(const int* __restrict__ batch) {
    int i = blockIdx.x * blockDim.x + threadIdx.x;
    if (i >= NN) return;
    int b = batch[i];
    int prev = (i == 0) ? -1 : batch[i - 1];
    for (int g = prev + 1; g <= b; g++) g_gstart[g] = i;
    if (i == NN - 1)
        for (int g = b + 1; g <= NG; g++) g_gstart[g] = NN;
}

// ---------------- fused mean-pool + FC ----------------
__global__ void k_poolfc(const float* __restrict__ fc_w, const float* __restrict__ fc_b,
                         float* __restrict__ out) {
    __shared__ float pm[DD];
    int g = blockIdx.x;
    int d = threadIdx.x;
    int s = g_gstart[g], e = g_gstart[g + 1];
    float acc = 0.f;
    for (int n = s; n < e; n++) acc += fmaxf(g_agg[n * DD + d], 0.f);
    float inv = 1.0f / fmaxf((float)(e - s), 1.0f);
    pm[d] = acc * inv;
    __syncthreads();
    if (d < NO) {
        float sum = fc_b[d];
        #pragma unroll 8
        for (int k = 0; k < DD; k++) sum += pm[k] * fc_w[k * NO + d];
        out[g * NO + d] = sum;
    }
}

// ---------------- launch ----------------
extern "C" void kernel_launch(void* const* d_in, const int* in_sizes, int n_in,
                              void* d_out, int out_size) {
    const int*   x     = (const int*)d_in[0];
    const int*   eidx  = (const int*)d_in[1];
    const int*   batch = (const int*)d_in[2];
    const float* embed = (const float*)d_in[3];
    const float* W0    = (const float*)d_in[4];
    const float* b0    = (const float*)d_in[5];
    const float* W1    = (const float*)d_in[6];
    const float* b1    = (const float*)d_in[7];
    const float* W2    = (const float*)d_in[8];
    const float* b2    = (const float*)d_in[9];
    const float* fc_w  = (const float*)d_in[10];
    const float* fc_b  = (const float*)d_in[11];
    float* out = (float*)d_out;

    const int* src = eidx;
    const int* dst = eidx + NE;

    void* p_degi;
    cudaGetSymbolAddress(&p_degi, g_degi);
    cudaMemsetAsync(p_degi, 0, NN * sizeof(int));

    // graph structure
    k_deg<<<(NE + 255) / 256, 256>>>(dst);
    k_scan<<<NCHUNK, SCAN_BLK>>>();
    k_fill<<<(NE + 255) / 256, 256>>>(src, dst);
    k_bound<<<(NN + 255) / 256, 256>>>(batch);

    // layer 0: embed-gather fused into aggregation
    k_t11<<<NT, DD>>>(embed, W0);
    k_agg0<<<NN / 8, 256>>>(b0, x);

    // layer 1
    k_gemm<<<NNP / 128, 256>>>(W1);
    k_agg<<<NN / 8, 256>>>(b1);

    // layer 2
    k_gemm<<<NNP / 128, 256>>>(W2);
    k_agg<<<NN / 8, 256>>>(b2);

    // pool + fc
    k_poolfc<<<NG, DD>>>(fc_w, fc_b, out);
}

// round 10
// speedup vs baseline: 1.6667x; 1.6665x over previous
#include <cuda_runtime.h>
#include <cuda_bf16.h>
#include <cuda_fp16.h>
#include <mma.h>

using namespace nvcuda;

#define NN 50000
#define NNP 50048              // padded to 391*128 for guard-free GEMM
#define NE 500000
#define NG 512
#define DD 128
#define NO 64
#define NT 11
#define SCAN_BLK 512
#define NCHUNK ((NNP + SCAN_BLK - 1) / SCAN_BLK)   // 98

// ---------------- device scratch ----------------
__device__ float  g_dinv[NNP];       // pads = 0
__device__ int    g_degi[NN];
__device__ int    g_rowstart[NN];
__device__ int    g_cursor[NN];
__device__ int    g_csrc[NE];
__device__ __half g_hw[NNP * DD];    // dinv[row] * (h @ W) in fp16
__device__ float  g_agg[NNP * DD];   // pre-relu layer output; pad rows stay 0
__device__ float  g_t11[NT * DD];    // embed @ W0
__device__ int    g_gstart[NG + 1];
__device__ int    g_chunksum[NCHUNK];

__device__ __forceinline__ float4 ld4(const float* p) { return *(const float4*)p; }
__device__ __forceinline__ void st4(float* p, float4 v) { *(float4*)p = v; }

// ---------------- degree count + graph boundaries (fused) ----------------
__global__ void k_deg(const int* __restrict__ dst, const int* __restrict__ batch) {
    int i = blockIdx.x * blockDim.x + threadIdx.x;
    if (i < NE) atomicAdd(&g_degi[dst[i]], 1);
    if (i < NN) {
        int b = batch[i];
        int prev = (i == 0) ? -1 : batch[i - 1];
        for (int g = prev + 1; g <= b; g++) g_gstart[g] = i;
        if (i == NN - 1)
            for (int g = b + 1; g <= NG; g++) g_gstart[g] = NN;
    }
}

// ---------------- scan phase 1 (+ dinv + cursor reset) and t11 (extra blocks) ----------------
__global__ void k_scan1(const float* __restrict__ embed, const float* __restrict__ W0) {
    int c = blockIdx.x;
    int tid = threadIdx.x;

    if (c >= NCHUNK) {
        // t11 = embed @ W0, one 11-row block per blockIdx
        __shared__ float er[DD];
        int r = c - NCHUNK;
        if (tid < DD) er[tid] = embed[r * DD + tid];
        __syncthreads();
        if (tid < DD) {
            float s = 0.f;
            #pragma unroll 8
            for (int k = 0; k < DD; k++) s += er[k] * W0[k * DD + tid];
            g_t11[r * DD + tid] = s;
        }
        return;
    }

    __shared__ int sh[SCAN_BLK];
    int i = c * SCAN_BLK + tid;
    int v = (i < NN) ? g_degi[i] : 0;
    if (i < NNP) g_dinv[i] = (i < NN) ? rsqrtf((float)v + 1.0f) : 0.0f;
    if (i < NN)  g_cursor[i] = 0;

    sh[tid] = v;
    __syncthreads();
    #pragma unroll
    for (int off = 1; off < SCAN_BLK; off <<= 1) {
        int t = (tid >= off) ? sh[tid - off] : 0;
        __syncthreads();
        sh[tid] += t;
        __syncthreads();
    }
    if (i < NN) g_rowstart[i] = sh[tid] - v;   // exclusive within chunk
    if (tid == SCAN_BLK - 1) g_chunksum[c] = sh[SCAN_BLK - 1];
}

// ---------------- scan phase 2: per-block chunk-prefix ----------------
__global__ void k_scan3() {
    __shared__ int soff;
    int c = blockIdx.x;
    if (threadIdx.x == 0) {
        int r = 0;
        for (int k = 0; k < c; k++) r += g_chunksum[k];
        soff = r;
    }
    __syncthreads();
    int i = c * SCAN_BLK + threadIdx.x;
    if (i < NN) g_rowstart[i] += soff;
}

// ---------------- CSR fill (index only, no weights) ----------------
__global__ void k_fill(const int* __restrict__ src, const int* __restrict__ dst) {
    int e = blockIdx.x * blockDim.x + threadIdx.x;
    if (e >= NE) return;
    int s = src[e], d = dst[e];
    int pos = atomicAdd(&g_cursor[d], 1);
    g_csrc[g_rowstart[d] + pos] = s;
}

// ---------------- layer-0: agg = b + dinv[n] * ( dinv[n]*t11[x[n]] + sum_s dinv[s]*t11[x[s]] ) ----------------
__global__ void k_agg0(const float* __restrict__ b, const int* __restrict__ x) {
    __shared__ float st[NT * DD];
    for (int i = threadIdx.x; i < NT * DD; i += 256) st[i] = g_t11[i];
    __syncthreads();

    int n = blockIdx.x * 8 + (threadIdx.x >> 5);
    int lane = threadIdx.x & 31;
    const float4* st4p = (const float4*)st;

    float dn = g_dinv[n];
    float4 hv = st4p[x[n] * 32 + lane];
    float4 acc;
    acc.x = hv.x * dn; acc.y = hv.y * dn;
    acc.z = hv.z * dn; acc.w = hv.w * dn;

    int beg = g_rowstart[n];
    int cnt = g_degi[n];
    int j = 0;
    for (; j + 4 <= cnt; j += 4) {
        int s0 = g_csrc[beg + j],     s1 = g_csrc[beg + j + 1];
        int s2 = g_csrc[beg + j + 2], s3 = g_csrc[beg + j + 3];
        float w0 = g_dinv[s0], w1 = g_dinv[s1];
        float w2 = g_dinv[s2], w3 = g_dinv[s3];
        float4 v0 = st4p[x[s0] * 32 + lane];
        float4 v1 = st4p[x[s1] * 32 + lane];
        float4 v2 = st4p[x[s2] * 32 + lane];
        float4 v3 = st4p[x[s3] * 32 + lane];
        acc.x += v0.x * w0 + v1.x * w1 + v2.x * w2 + v3.x * w3;
        acc.y += v0.y * w0 + v1.y * w1 + v2.y * w2 + v3.y * w3;
        acc.z += v0.z * w0 + v1.z * w1 + v2.z * w2 + v3.z * w3;
        acc.w += v0.w * w0 + v1.w * w1 + v2.w * w2 + v3.w * w3;
    }
    for (; j < cnt; j++) {
        int s0 = g_csrc[beg + j];
        float w0 = g_dinv[s0];
        float4 v0 = st4p[x[s0] * 32 + lane];
        acc.x += v0.x * w0; acc.y += v0.y * w0;
        acc.z += v0.z * w0; acc.w += v0.w * w0;
    }
    float4 bv = ld4(&b[lane * 4]);
    acc.x = bv.x + acc.x * dn;
    acc.y = bv.y + acc.y * dn;
    acc.z = bv.z + acc.z * dn;
    acc.w = bv.w + acc.w * dn;
    st4(&g_agg[n * DD + lane * 4], acc);
}

// ---------------- layers 1,2: agg = b + dinv[n] * ( shw[n] + sum_s shw[s] ), shw pre-scaled fp16 ----------------
__device__ __forceinline__ void h4add(uint2 h, float4& acc) {
    float2 f01 = __half22float2(*(__half2*)&h.x);
    float2 f23 = __half22float2(*(__half2*)&h.y);
    acc.x += f01.x; acc.y += f01.y;
    acc.z += f23.x; acc.w += f23.y;
}

__global__ void k_agg(const float* __restrict__ b) {
    int n = blockIdx.x * 8 + (threadIdx.x >> 5);
    int lane = threadIdx.x & 31;
    const uint2* hw8 = (const uint2*)g_hw;    // 4 halves per uint2; row = 32 uint2

    float dn = g_dinv[n];
    float4 acc = make_float4(0.f, 0.f, 0.f, 0.f);
    h4add(hw8[n * 32 + lane], acc);           // self term (pre-scaled)

    int beg = g_rowstart[n];
    int cnt = g_degi[n];
    int j = 0;
    for (; j + 8 <= cnt; j += 8) {
        int s0 = g_csrc[beg + j],     s1 = g_csrc[beg + j + 1];
        int s2 = g_csrc[beg + j + 2], s3 = g_csrc[beg + j + 3];
        int s4 = g_csrc[beg + j + 4], s5 = g_csrc[beg + j + 5];
        int s6 = g_csrc[beg + j + 6], s7 = g_csrc[beg + j + 7];
        uint2 v0 = hw8[s0 * 32 + lane];
        uint2 v1 = hw8[s1 * 32 + lane];
        uint2 v2 = hw8[s2 * 32 + lane];
        uint2 v3 = hw8[s3 * 32 + lane];
        uint2 v4 = hw8[s4 * 32 + lane];
        uint2 v5 = hw8[s5 * 32 + lane];
        uint2 v6 = hw8[s6 * 32 + lane];
        uint2 v7 = hw8[s7 * 32 + lane];
        h4add(v0, acc); h4add(v1, acc); h4add(v2, acc); h4add(v3, acc);
        h4add(v4, acc); h4add(v5, acc); h4add(v6, acc); h4add(v7, acc);
    }
    for (; j < cnt; j++) {
        h4add(hw8[g_csrc[beg + j] * 32 + lane], acc);
    }
    float4 bv = ld4(&b[lane * 4]);
    acc.x = bv.x + acc.x * dn;
    acc.y = bv.y + acc.y * dn;
    acc.z = bv.z + acc.z * dn;
    acc.w = bv.w + acc.w * dn;
    st4(&g_agg[n * DD + lane * 4], acc);
}

// ---------------- tf32 GEMM: hw = fp16( dinv[row] * (relu(agg) @ W) ) ----------------
#define APAD 40     // A smem row stride (floats)
#define BPAD 136    // B smem row stride (floats)
__global__ __launch_bounds__(256) void k_gemm(const float* __restrict__ W) {
    __shared__ float As[128 * APAD];
    __shared__ float Bs[32 * BPAD];
    int m0 = blockIdx.x * 128;
    int tid = threadIdx.x;
    int wid = tid >> 5;
    int lane = tid & 31;
    int warp_m = wid >> 1;        // 0..3
    int warp_n = wid & 1;         // 0..1

    wmma::fragment<wmma::accumulator, 16, 16, 8, float> c[2][4];
    #pragma unroll
    for (int i = 0; i < 2; i++)
        #pragma unroll
        for (int j = 0; j < 4; j++) wmma::fill_fragment(c[i][j], 0.0f);

    for (int k0 = 0; k0 < DD; k0 += 32) {
        #pragma unroll
        for (int t = 0; t < 4; t++) {
            int f = tid + t * 256;
            int row = f >> 3, c4 = (f & 7) * 4;
            float4 v = ld4(&g_agg[(m0 + row) * DD + k0 + c4]);
            float* d = &As[row * APAD + c4];
            d[0] = wmma::__float_to_tf32(fmaxf(v.x, 0.f));
            d[1] = wmma::__float_to_tf32(fmaxf(v.y, 0.f));
            d[2] = wmma::__float_to_tf32(fmaxf(v.z, 0.f));
            d[3] = wmma::__float_to_tf32(fmaxf(v.w, 0.f));
        }
        #pragma unroll
        for (int t = 0; t < 4; t++) {
            int f = tid + t * 256;
            int row = f >> 5, c4 = (f & 31) * 4;
            float4 v = ld4(&W[(k0 + row) * DD + c4]);
            float* d = &Bs[row * BPAD + c4];
            d[0] = wmma::__float_to_tf32(v.x);
            d[1] = wmma::__float_to_tf32(v.y);
            d[2] = wmma::__float_to_tf32(v.z);
            d[3] = wmma::__float_to_tf32(v.w);
        }
        __syncthreads();
        #pragma unroll
        for (int kk = 0; kk < 4; kk++) {
            wmma::fragment<wmma::matrix_a, 16, 16, 8, wmma::precision::tf32, wmma::row_major> a[2];
            wmma::fragment<wmma::matrix_b, 16, 16, 8, wmma::precision::tf32, wmma::row_major> bfr[4];
            #pragma unroll
            for (int i = 0; i < 2; i++)
                wmma::load_matrix_sync(a[i], &As[(warp_m * 32 + i * 16) * APAD + kk * 8], APAD);
            #pragma unroll
            for (int j = 0; j < 4; j++)
                wmma::load_matrix_sync(bfr[j], &Bs[(kk * 8) * BPAD + warp_n * 64 + j * 16], BPAD);
            #pragma unroll
            for (int i = 0; i < 2; i++)
                #pragma unroll
                for (int j = 0; j < 4; j++)
                    wmma::mma_sync(c[i][j], a[i], bfr[j], c[i][j]);
        }
        __syncthreads();
    }

    // epilogue: stage frags in smem, scale by dinv[row], convert fp16, 16B stores
    float* stg = &As[wid * 272];            // 272 floats per warp, 16B aligned
    int srow = lane >> 1;
    int scol = (lane & 1) * 8;
    #pragma unroll
    for (int i = 0; i < 2; i++) {
        #pragma unroll
        for (int j = 0; j < 4; j++) {
            wmma::store_matrix_sync(stg, c[i][j], 16, wmma::mem_row_major);
            __syncwarp();
            int grow = m0 + warp_m * 32 + i * 16 + srow;
            float dv = g_dinv[grow];
            float4 f0 = *(float4*)&stg[srow * 16 + scol];
            float4 f1 = *(float4*)&stg[srow * 16 + scol + 4];
            __half2 p0 = __floats2half2_rn(f0.x * dv, f0.y * dv);
            __half2 p1 = __floats2half2_rn(f0.z * dv, f0.w * dv);
            __half2 p2 = __floats2half2_rn(f1.x * dv, f1.y * dv);
            __half2 p3 = __floats2half2_rn(f1.z * dv, f1.w * dv);
            uint4 pk = make_uint4(*(unsigned*)&p0, *(unsigned*)&p1,
                                  *(unsigned*)&p2, *(unsigned*)&p3);
            *(uint4*)&g_hw[grow * DD + warp_n * 64 + j * 16 + scol] = pk;
            __syncwarp();
        }
    }
}

// ---------------- fused mean-pool + FC ----------------
__global__ void k_poolfc(const float* __restrict__ fc_w, const float* __restrict__ fc_b,
                         float* __restrict__ out) {
    __shared__ float pm[DD];
    int g = blockIdx.x;
    int d = threadIdx.x;
    int s = g_gstart[g], e = g_gstart[g + 1];
    float acc = 0.f;
    for (int n = s; n < e; n++) acc += fmaxf(g_agg[n * DD + d], 0.f);
    float inv = 1.0f / fmaxf((float)(e - s), 1.0f);
    pm[d] = acc * inv;
    __syncthreads();
    if (d < NO) {
        float sum = fc_b[d];
        #pragma unroll 8
        for (int k = 0; k < DD; k++) sum += pm[k] * fc_w[k * NO + d];
        out[g * NO + d] = sum;
    }
}

// ---------------- launch ----------------
extern "C" void kernel_launch(void* const* d_in, const int* in_sizes, int n_in,
                              void* d_out, int out_size) {
    const int*   x     = (const int*)d_in[0];
    const int*   eidx  = (const int*)d_in[1];
    const int*   batch = (const int*)d_in[2];
    const float* embed = (const float*)d_in[3];
    const float* W0    = (const float*)d_in[4];
    const float* b0    = (const float*)d_in[5];
    const float* W1    = (const float*)d_in[6];
    const float* b1    = (const float*)d_in[7];
    const float* W2    = (const float*)d_in[8];
    const float* b2    = (const float*)d_in[9];
    const float* fc_w  = (const float*)d_in[10];
    const float* fc_b  = (const float*)d_in[11];
    float* out = (float*)d_out;

    const int* src = eidx;
    const int* dst = eidx + NE;

    void* p_degi;
    cudaGetSymbolAddress(&p_degi, g_degi);
    cudaMemsetAsync(p_degi, 0, NN * sizeof(int));

    // graph structure (+ boundaries fused into deg, t11 fused into scan1)
    k_deg<<<(NE + 255) / 256, 256>>>(dst, batch);
    k_scan1<<<NCHUNK + NT, SCAN_BLK>>>(embed, W0);
    k_scan3<<<NCHUNK, SCAN_BLK>>>();
    k_fill<<<(NE + 255) / 256, 256>>>(src, dst);

    // layer 0: embed-gather fused into aggregation
    k_agg0<<<NN / 8, 256>>>(b0, x);

    // layer 1
    k_gemm<<<NNP / 128, 256>>>(W1);
    k_agg<<<NN / 8, 256>>>(b1);

    // layer 2
    k_gemm<<<NNP / 128, 256>>>(W2);
    k_agg<<<NN / 8, 256>>>(b2);

    // pool + fc
    k_poolfc<<<NG, DD>>>(fc_w, fc_b, out);
}

// round 11
// speedup vs baseline: 1.6866x; 1.0119x over previous
#include <cuda_runtime.h>
#include <cuda_bf16.h>
#include <cuda_fp16.h>
#include <mma.h>

using namespace nvcuda;

#define NN 50000
#define NNP 50048              // padded to 391*128 for guard-free GEMM
#define NE 500000
#define NG 512
#define DD 128
#define NO 64
#define NT 11
#define SCAN_BLK 512
#define NCHUNK ((NNP + SCAN_BLK - 1) / SCAN_BLK)   // 98

// ---------------- device scratch ----------------
__device__ float  g_dinv[NNP];       // pads = 0
__device__ int    g_degi[NN];
__device__ int    g_rowstart[NN];    // after k_fill: row END (start + deg)
__device__ int    g_csrc[NE];
__device__ __half g_hw[NNP * DD];    // dinv[row] * (h @ W) in fp16
__device__ float  g_agg[NNP * DD];   // pre-relu layer output; pad rows stay 0
__device__ float  g_t11[NT * DD];    // embed @ W0
__device__ int    g_gstart[NG + 1];
__device__ int    g_chunksum[NCHUNK];
__device__ float  g_pooled[NG * DD];

__device__ __forceinline__ float4 ld4(const float* p) { return *(const float4*)p; }
__device__ __forceinline__ void st4(float* p, float4 v) { *(float4*)p = v; }

// ---------------- degree count + graph boundaries (fused) ----------------
__global__ void k_deg(const int* __restrict__ dst, const int* __restrict__ batch) {
    int i = blockIdx.x * blockDim.x + threadIdx.x;
    if (i < NE) atomicAdd(&g_degi[dst[i]], 1);
    if (i < NN) {
        int b = batch[i];
        int prev = (i == 0) ? -1 : batch[i - 1];
        for (int g = prev + 1; g <= b; g++) g_gstart[g] = i;
        if (i == NN - 1)
            for (int g = b + 1; g <= NG; g++) g_gstart[g] = NN;
    }
}

// ---------------- scan phase 1 (+ dinv) and t11 (extra blocks) ----------------
__global__ void k_scan1(const float* __restrict__ embed, const float* __restrict__ W0) {
    int c = blockIdx.x;
    int tid = threadIdx.x;

    if (c >= NCHUNK) {
        // t11 = embed @ W0, one row per extra block
        __shared__ float er[DD];
        int r = c - NCHUNK;
        if (tid < DD) er[tid] = embed[r * DD + tid];
        __syncthreads();
        if (tid < DD) {
            float s = 0.f;
            #pragma unroll 8
            for (int k = 0; k < DD; k++) s += er[k] * W0[k * DD + tid];
            g_t11[r * DD + tid] = s;
        }
        return;
    }

    __shared__ int sh[SCAN_BLK];
    int i = c * SCAN_BLK + tid;
    int v = (i < NN) ? g_degi[i] : 0;
    if (i < NNP) g_dinv[i] = (i < NN) ? rsqrtf((float)v + 1.0f) : 0.0f;

    sh[tid] = v;
    __syncthreads();
    #pragma unroll
    for (int off = 1; off < SCAN_BLK; off <<= 1) {
        int t = (tid >= off) ? sh[tid - off] : 0;
        __syncthreads();
        sh[tid] += t;
        __syncthreads();
    }
    if (i < NN) g_rowstart[i] = sh[tid] - v;   // exclusive within chunk
    if (tid == SCAN_BLK - 1) g_chunksum[c] = sh[SCAN_BLK - 1];
}

// ---------------- scan phase 2: per-block chunk-prefix ----------------
__global__ void k_scan3() {
    __shared__ int soff;
    int c = blockIdx.x;
    if (threadIdx.x == 0) {
        int r = 0;
        for (int k = 0; k < c; k++) r += g_chunksum[k];
        soff = r;
    }
    __syncthreads();
    int i = c * SCAN_BLK + threadIdx.x;
    if (i < NN) g_rowstart[i] += soff;
}

// ---------------- CSR fill: rowstart doubles as cursor (ends at row END) ----------------
__global__ void k_fill(const int* __restrict__ src, const int* __restrict__ dst) {
    int e = blockIdx.x * blockDim.x + threadIdx.x;
    if (e >= NE) return;
    int s = src[e], d = dst[e];
    int pos = atomicAdd(&g_rowstart[d], 1);
    g_csrc[pos] = s;
}

// ---------------- layer-0: agg = b + dinv[n] * ( dinv[n]*t11[x[n]] + sum_s dinv[s]*t11[x[s]] ) ----------------
__global__ void k_agg0(const float* __restrict__ b, const int* __restrict__ x) {
    __shared__ float st[NT * DD];
    for (int i = threadIdx.x; i < NT * DD; i += 256) st[i] = g_t11[i];
    __syncthreads();

    int n = blockIdx.x * 8 + (threadIdx.x >> 5);
    int lane = threadIdx.x & 31;
    const float4* st4p = (const float4*)st;

    float dn = g_dinv[n];
    float4 hv = st4p[x[n] * 32 + lane];
    float4 acc;
    acc.x = hv.x * dn; acc.y = hv.y * dn;
    acc.z = hv.z * dn; acc.w = hv.w * dn;

    int cnt = g_degi[n];
    int beg = g_rowstart[n] - cnt;     // rowstart holds row END after k_fill
    int j = 0;
    for (; j + 4 <= cnt; j += 4) {
        int s0 = g_csrc[beg + j],     s1 = g_csrc[beg + j + 1];
        int s2 = g_csrc[beg + j + 2], s3 = g_csrc[beg + j + 3];
        float w0 = g_dinv[s0], w1 = g_dinv[s1];
        float w2 = g_dinv[s2], w3 = g_dinv[s3];
        float4 v0 = st4p[x[s0] * 32 + lane];
        float4 v1 = st4p[x[s1] * 32 + lane];
        float4 v2 = st4p[x[s2] * 32 + lane];
        float4 v3 = st4p[x[s3] * 32 + lane];
        acc.x += v0.x * w0 + v1.x * w1 + v2.x * w2 + v3.x * w3;
        acc.y += v0.y * w0 + v1.y * w1 + v2.y * w2 + v3.y * w3;
        acc.z += v0.z * w0 + v1.z * w1 + v2.z * w2 + v3.z * w3;
        acc.w += v0.w * w0 + v1.w * w1 + v2.w * w2 + v3.w * w3;
    }
    for (; j < cnt; j++) {
        int s0 = g_csrc[beg + j];
        float w0 = g_dinv[s0];
        float4 v0 = st4p[x[s0] * 32 + lane];
        acc.x += v0.x * w0; acc.y += v0.y * w0;
        acc.z += v0.z * w0; acc.w += v0.w * w0;
    }
    float4 bv = ld4(&b[lane * 4]);
    acc.x = bv.x + acc.x * dn;
    acc.y = bv.y + acc.y * dn;
    acc.z = bv.z + acc.z * dn;
    acc.w = bv.w + acc.w * dn;
    st4(&g_agg[n * DD + lane * 4], acc);
}

// ---------------- fp16 edge-sum core ----------------
__device__ __forceinline__ void h4add(uint2 h, float4& acc) {
    float2 f01 = __half22float2(*(__half2*)&h.x);
    float2 f23 = __half22float2(*(__half2*)&h.y);
    acc.x += f01.x; acc.y += f01.y;
    acc.z += f23.x; acc.w += f23.y;
}

__device__ __forceinline__ float4 agg_node(int n, int lane, const float* __restrict__ b) {
    const uint2* hw8 = (const uint2*)g_hw;
    float dn = g_dinv[n];
    float4 acc = make_float4(0.f, 0.f, 0.f, 0.f);
    h4add(hw8[n * 32 + lane], acc);           // self term (pre-scaled)

    int cnt = g_degi[n];
    int beg = g_rowstart[n] - cnt;
    int j = 0;
    for (; j + 8 <= cnt; j += 8) {
        int s0 = g_csrc[beg + j],     s1 = g_csrc[beg + j + 1];
        int s2 = g_csrc[beg + j + 2], s3 = g_csrc[beg + j + 3];
        int s4 = g_csrc[beg + j + 4], s5 = g_csrc[beg + j + 5];
        int s6 = g_csrc[beg + j + 6], s7 = g_csrc[beg + j + 7];
        uint2 v0 = hw8[s0 * 32 + lane];
        uint2 v1 = hw8[s1 * 32 + lane];
        uint2 v2 = hw8[s2 * 32 + lane];
        uint2 v3 = hw8[s3 * 32 + lane];
        uint2 v4 = hw8[s4 * 32 + lane];
        uint2 v5 = hw8[s5 * 32 + lane];
        uint2 v6 = hw8[s6 * 32 + lane];
        uint2 v7 = hw8[s7 * 32 + lane];
        h4add(v0, acc); h4add(v1, acc); h4add(v2, acc); h4add(v3, acc);
        h4add(v4, acc); h4add(v5, acc); h4add(v6, acc); h4add(v7, acc);
    }
    for (; j < cnt; j++) {
        h4add(hw8[g_csrc[beg + j] * 32 + lane], acc);
    }
    float4 bv = ld4(&b[lane * 4]);
    acc.x = bv.x + acc.x * dn;
    acc.y = bv.y + acc.y * dn;
    acc.z = bv.z + acc.z * dn;
    acc.w = bv.w + acc.w * dn;
    return acc;
}

// ---------------- layer-1 aggregation: write g_agg ----------------
__global__ void k_agg(const float* __restrict__ b) {
    int n = blockIdx.x * 8 + (threadIdx.x >> 5);
    int lane = threadIdx.x & 31;
    float4 acc = agg_node(n, lane, b);
    st4(&g_agg[n * DD + lane * 4], acc);
}

// ---------------- layer-2 aggregation fused with relu + pooled scatter ----------------
__global__ void k_agg2pool(const float* __restrict__ b, const int* __restrict__ batch) {
    __shared__ float sacc[8][DD];
    __shared__ int   sg[8];
    int w = threadIdx.x >> 5;
    int n = blockIdx.x * 8 + w;
    int lane = threadIdx.x & 31;
    float4 acc = agg_node(n, lane, b);
    // relu then stage
    sacc[w][lane * 4 + 0] = fmaxf(acc.x, 0.f);
    sacc[w][lane * 4 + 1] = fmaxf(acc.y, 0.f);
    sacc[w][lane * 4 + 2] = fmaxf(acc.z, 0.f);
    sacc[w][lane * 4 + 3] = fmaxf(acc.w, 0.f);
    if (lane == 0) sg[w] = batch[n];
    __syncthreads();
    // run-length reduce across the 8 (sorted-batch) nodes, one thread per feature
    int d = threadIdx.x;
    if (d < DD) {
        float run = sacc[0][d];
        int cg = sg[0];
        #pragma unroll
        for (int k = 1; k < 8; k++) {
            int gk = sg[k];
            float vk = sacc[k][d];
            if (gk == cg) run += vk;
            else { atomicAdd(&g_pooled[cg * DD + d], run); cg = gk; run = vk; }
        }
        atomicAdd(&g_pooled[cg * DD + d], run);
    }
}

// ---------------- tf32 GEMM: hw = fp16( dinv[row] * (relu(agg) @ W) ) ----------------
#define APAD 40     // A smem row stride (floats)
#define BPAD 136    // B smem row stride (floats)
__global__ __launch_bounds__(256) void k_gemm(const float* __restrict__ W) {
    __shared__ float As[128 * APAD];
    __shared__ float Bs[32 * BPAD];
    int m0 = blockIdx.x * 128;
    int tid = threadIdx.x;
    int wid = tid >> 5;
    int lane = tid & 31;
    int warp_m = wid >> 1;        // 0..3
    int warp_n = wid & 1;         // 0..1

    wmma::fragment<wmma::accumulator, 16, 16, 8, float> c[2][4];
    #pragma unroll
    for (int i = 0; i < 2; i++)
        #pragma unroll
        for (int j = 0; j < 4; j++) wmma::fill_fragment(c[i][j], 0.0f);

    for (int k0 = 0; k0 < DD; k0 += 32) {
        #pragma unroll
        for (int t = 0; t < 4; t++) {
            int f = tid + t * 256;
            int row = f >> 3, c4 = (f & 7) * 4;
            float4 v = ld4(&g_agg[(m0 + row) * DD + k0 + c4]);
            float* d = &As[row * APAD + c4];
            d[0] = wmma::__float_to_tf32(fmaxf(v.x, 0.f));
            d[1] = wmma::__float_to_tf32(fmaxf(v.y, 0.f));
            d[2] = wmma::__float_to_tf32(fmaxf(v.z, 0.f));
            d[3] = wmma::__float_to_tf32(fmaxf(v.w, 0.f));
        }
        #pragma unroll
        for (int t = 0; t < 4; t++) {
            int f = tid + t * 256;
            int row = f >> 5, c4 = (f & 31) * 4;
            float4 v = ld4(&W[(k0 + row) * DD + c4]);
            float* d = &Bs[row * BPAD + c4];
            d[0] = wmma::__float_to_tf32(v.x);
            d[1] = wmma::__float_to_tf32(v.y);
            d[2] = wmma::__float_to_tf32(v.z);
            d[3] = wmma::__float_to_tf32(v.w);
        }
        __syncthreads();
        #pragma unroll
        for (int kk = 0; kk < 4; kk++) {
            wmma::fragment<wmma::matrix_a, 16, 16, 8, wmma::precision::tf32, wmma::row_major> a[2];
            wmma::fragment<wmma::matrix_b, 16, 16, 8, wmma::precision::tf32, wmma::row_major> bfr[4];
            #pragma unroll
            for (int i = 0; i < 2; i++)
                wmma::load_matrix_sync(a[i], &As[(warp_m * 32 + i * 16) * APAD + kk * 8], APAD);
            #pragma unroll
            for (int j = 0; j < 4; j++)
                wmma::load_matrix_sync(bfr[j], &Bs[(kk * 8) * BPAD + warp_n * 64 + j * 16], BPAD);
            #pragma unroll
            for (int i = 0; i < 2; i++)
                #pragma unroll
                for (int j = 0; j < 4; j++)
                    wmma::mma_sync(c[i][j], a[i], bfr[j], c[i][j]);
        }
        __syncthreads();
    }

    // epilogue: stage frags in smem, scale by dinv[row], convert fp16, 16B stores
    float* stg = &As[wid * 272];            // 272 floats per warp, 16B aligned
    int srow = lane >> 1;
    int scol = (lane & 1) * 8;
    #pragma unroll
    for (int i = 0; i < 2; i++) {
        #pragma unroll
        for (int j = 0; j < 4; j++) {
            wmma::store_matrix_sync(stg, c[i][j], 16, wmma::mem_row_major);
            __syncwarp();
            int grow = m0 + warp_m * 32 + i * 16 + srow;
            float dv = g_dinv[grow];
            float4 f0 = *(float4*)&stg[srow * 16 + scol];
            float4 f1 = *(float4*)&stg[srow * 16 + scol + 4];
            __half2 p0 = __floats2half2_rn(f0.x * dv, f0.y * dv);
            __half2 p1 = __floats2half2_rn(f0.z * dv, f0.w * dv);
            __half2 p2 = __floats2half2_rn(f1.x * dv, f1.y * dv);
            __half2 p3 = __floats2half2_rn(f1.z * dv, f1.w * dv);
            uint4 pk = make_uint4(*(unsigned*)&p0, *(unsigned*)&p1,
                                  *(unsigned*)&p2, *(unsigned*)&p3);
            *(uint4*)&g_hw[grow * DD + warp_n * 64 + j * 16 + scol] = pk;
            __syncwarp();
        }
    }
}

// ---------------- final: divide pooled by counts + FC ----------------
__global__ void k_fc(const float* __restrict__ fc_w, const float* __restrict__ fc_b,
                     float* __restrict__ out) {
    __shared__ float pm[DD];
    int g = blockIdx.x;
    int d = threadIdx.x;              // 128
    int cnt = g_gstart[g + 1] - g_gstart[g];
    float inv = 1.0f / fmaxf((float)cnt, 1.0f);
    pm[d] = g_pooled[g * DD + d] * inv;
    __syncthreads();
    if (d < NO) {
        float sum = fc_b[d];
        #pragma unroll 8
        for (int k = 0; k < DD; k++) sum += pm[k] * fc_w[k * NO + d];
        out[g * NO + d] = sum;
    }
}

// ---------------- launch ----------------
extern "C" void kernel_launch(void* const* d_in, const int* in_sizes, int n_in,
                              void* d_out, int out_size) {
    const int*   x     = (const int*)d_in[0];
    const int*   eidx  = (const int*)d_in[1];
    const int*   batch = (const int*)d_in[2];
    const float* embed = (const float*)d_in[3];
    const float* W0    = (const float*)d_in[4];
    const float* b0    = (const float*)d_in[5];
    const float* W1    = (const float*)d_in[6];
    const float* b1    = (const float*)d_in[7];
    const float* W2    = (const float*)d_in[8];
    const float* b2    = (const float*)d_in[9];
    const float* fc_w  = (const float*)d_in[10];
    const float* fc_b  = (const float*)d_in[11];
    float* out = (float*)d_out;

    const int* src = eidx;
    const int* dst = eidx + NE;

    void *p_degi, *p_pooled;
    cudaGetSymbolAddress(&p_degi, g_degi);
    cudaGetSymbolAddress(&p_pooled, g_pooled);
    cudaMemsetAsync(p_degi, 0, NN * sizeof(int));
    cudaMemsetAsync(p_pooled, 0, NG * DD * sizeof(float));

    // graph structure
    k_deg<<<(NE + 255) / 256, 256>>>(dst, batch);
    k_scan1<<<NCHUNK + NT, SCAN_BLK>>>(embed, W0);
    k_scan3<<<NCHUNK, SCAN_BLK>>>();
    k_fill<<<(NE + 255) / 256, 256>>>(src, dst);

    // layer 0: embed-gather fused into aggregation
    k_agg0<<<NN / 8, 256>>>(b0, x);

    // layer 1
    k_gemm<<<NNP / 128, 256>>>(W1);
    k_agg<<<NN / 8, 256>>>(b1);

    // layer 2 (aggregation fused with pooling)
    k_gemm<<<NNP / 128, 256>>>(W2);
    k_agg2pool<<<NN / 8, 256>>>(b2, batch);

    // fc
    k_fc<<<NG, DD>>>(fc_w, fc_b, out);
}

// round 12
// speedup vs baseline: 2.3593x; 1.3989x over previous
#include <cuda_runtime.h>
#include <cuda_bf16.h>
#include <cuda_fp16.h>
#include <mma.h>

using namespace nvcuda;

#define NN 50000
#define NNP 50048              // padded to 391*128 for guard-free GEMM
#define NE 500000
#define NG 512
#define DD 128
#define NO 64
#define NT 11
#define SCAN_BLK 512
#define NCHUNK ((NNP + SCAN_BLK - 1) / SCAN_BLK)   // 98

// ---------------- device scratch ----------------
__device__ float  g_dinv[NNP];       // pads = 0
__device__ int2   g_xd[NN];          // {x[n], bitcast(dinv[n])}
__device__ int    g_degi[NN];
__device__ int    g_rowstart[NN];    // after k_fill: row END (start + deg)
__device__ int    g_csrc[NE];
__device__ __half g_hw[NNP * DD];    // dinv[row] * (h @ W) in fp16
__device__ __half g_agg[NNP * DD];   // pre-relu layer output fp16; pad rows stay 0
__device__ float  g_t11[NT * DD];    // embed @ W0
__device__ int    g_gstart[NG + 1];
__device__ int    g_chunksum[NCHUNK];
__device__ float  g_pooled[NG * DD];

__device__ __forceinline__ float4 ld4(const float* p) { return *(const float4*)p; }
__device__ __forceinline__ void st4(float* p, float4 v) { *(float4*)p = v; }

// pack float4 -> 4 halves (uint2)
__device__ __forceinline__ uint2 f4toh4(float4 v) {
    __half2 p0 = __floats2half2_rn(v.x, v.y);
    __half2 p1 = __floats2half2_rn(v.z, v.w);
    return make_uint2(*(unsigned*)&p0, *(unsigned*)&p1);
}

// ---------------- degree count + graph boundaries + pooled zero (fused) ----------------
__global__ void k_deg(const int* __restrict__ dst, const int* __restrict__ batch) {
    int i = blockIdx.x * blockDim.x + threadIdx.x;
    if (i < NE) atomicAdd(&g_degi[dst[i]], 1);
    if (i < NG * DD) g_pooled[i] = 0.f;
    if (i < NN) {
        int b = batch[i];
        int prev = (i == 0) ? -1 : batch[i - 1];
        for (int g = prev + 1; g <= b; g++) g_gstart[g] = i;
        if (i == NN - 1)
            for (int g = b + 1; g <= NG; g++) g_gstart[g] = NN;
    }
}

// ---------------- scan phase 1 (+ dinv + xd pack) and t11 (extra blocks) ----------------
__global__ void k_scan1(const float* __restrict__ embed, const float* __restrict__ W0,
                        const int* __restrict__ x) {
    int c = blockIdx.x;
    int tid = threadIdx.x;

    if (c >= NCHUNK) {
        // t11 = embed @ W0, one row per extra block
        __shared__ float er[DD];
        int r = c - NCHUNK;
        if (tid < DD) er[tid] = embed[r * DD + tid];
        __syncthreads();
        if (tid < DD) {
            float s = 0.f;
            #pragma unroll 8
            for (int k = 0; k < DD; k++) s += er[k] * W0[k * DD + tid];
            g_t11[r * DD + tid] = s;
        }
        return;
    }

    __shared__ int sh[SCAN_BLK];
    int i = c * SCAN_BLK + tid;
    int v = (i < NN) ? g_degi[i] : 0;
    float dv = rsqrtf((float)v + 1.0f);
    if (i < NNP) g_dinv[i] = (i < NN) ? dv : 0.0f;
    if (i < NN)  g_xd[i] = make_int2(x[i], __float_as_int(dv));

    sh[tid] = v;
    __syncthreads();
    #pragma unroll
    for (int off = 1; off < SCAN_BLK; off <<= 1) {
        int t = (tid >= off) ? sh[tid - off] : 0;
        __syncthreads();
        sh[tid] += t;
        __syncthreads();
    }
    if (i < NN) g_rowstart[i] = sh[tid] - v;   // exclusive within chunk
    if (tid == SCAN_BLK - 1) g_chunksum[c] = sh[SCAN_BLK - 1];
}

// ---------------- scan phase 2: per-block chunk-prefix ----------------
__global__ void k_scan3() {
    __shared__ int soff;
    int c = blockIdx.x;
    if (threadIdx.x == 0) {
        int r = 0;
        for (int k = 0; k < c; k++) r += g_chunksum[k];
        soff = r;
    }
    __syncthreads();
    int i = c * SCAN_BLK + threadIdx.x;
    if (i < NN) g_rowstart[i] += soff;
}

// ---------------- CSR fill: rowstart doubles as cursor (ends at row END) ----------------
__global__ void k_fill(const int* __restrict__ src, const int* __restrict__ dst) {
    int e = blockIdx.x * blockDim.x + threadIdx.x;
    if (e >= NE) return;
    int s = src[e], d = dst[e];
    int pos = atomicAdd(&g_rowstart[d], 1);
    g_csrc[pos] = s;
}

// ---------------- layer-0: agg = b + dinv[n]*( dinv[n]*t11[x[n]] + sum_s dinv[s]*t11[x[s]] ) ----------------
__global__ void k_agg0(const float* __restrict__ b) {
    __shared__ float st[NT * DD];
    for (int i = threadIdx.x; i < NT * DD; i += 256) st[i] = g_t11[i];
    __syncthreads();

    int n = blockIdx.x * 8 + (threadIdx.x >> 5);
    int lane = threadIdx.x & 31;
    const float4* st4p = (const float4*)st;

    int2 xdn = g_xd[n];
    float dn = __int_as_float(xdn.y);
    float4 hv = st4p[xdn.x * 32 + lane];
    float4 acc;
    acc.x = hv.x * dn; acc.y = hv.y * dn;
    acc.z = hv.z * dn; acc.w = hv.w * dn;

    int cnt = g_degi[n];
    int beg = g_rowstart[n] - cnt;     // rowstart holds row END after k_fill
    int j = 0;
    for (; j + 4 <= cnt; j += 4) {
        int2 x0 = g_xd[g_csrc[beg + j]];
        int2 x1 = g_xd[g_csrc[beg + j + 1]];
        int2 x2 = g_xd[g_csrc[beg + j + 2]];
        int2 x3 = g_xd[g_csrc[beg + j + 3]];
        float w0 = __int_as_float(x0.y), w1 = __int_as_float(x1.y);
        float w2 = __int_as_float(x2.y), w3 = __int_as_float(x3.y);
        float4 v0 = st4p[x0.x * 32 + lane];
        float4 v1 = st4p[x1.x * 32 + lane];
        float4 v2 = st4p[x2.x * 32 + lane];
        float4 v3 = st4p[x3.x * 32 + lane];
        acc.x += v0.x * w0 + v1.x * w1 + v2.x * w2 + v3.x * w3;
        acc.y += v0.y * w0 + v1.y * w1 + v2.y * w2 + v3.y * w3;
        acc.z += v0.z * w0 + v1.z * w1 + v2.z * w2 + v3.z * w3;
        acc.w += v0.w * w0 + v1.w * w1 + v2.w * w2 + v3.w * w3;
    }
    for (; j < cnt; j++) {
        int2 x0 = g_xd[g_csrc[beg + j]];
        float w0 = __int_as_float(x0.y);
        float4 v0 = st4p[x0.x * 32 + lane];
        acc.x += v0.x * w0; acc.y += v0.y * w0;
        acc.z += v0.z * w0; acc.w += v0.w * w0;
    }
    float4 bv = ld4(&b[lane * 4]);
    acc.x = bv.x + acc.x * dn;
    acc.y = bv.y + acc.y * dn;
    acc.z = bv.z + acc.z * dn;
    acc.w = bv.w + acc.w * dn;
    *(uint2*)&g_agg[n * DD + lane * 4] = f4toh4(acc);
}

// ---------------- fp16 edge-sum core ----------------
__device__ __forceinline__ void h4add(uint2 h, float4& acc) {
    float2 f01 = __half22float2(*(__half2*)&h.x);
    float2 f23 = __half22float2(*(__half2*)&h.y);
    acc.x += f01.x; acc.y += f01.y;
    acc.z += f23.x; acc.w += f23.y;
}

__device__ __forceinline__ float4 agg_node(int n, int lane, const float* __restrict__ b) {
    const uint2* hw8 = (const uint2*)g_hw;
    float dn = g_dinv[n];
    float4 acc = make_float4(0.f, 0.f, 0.f, 0.f);
    h4add(hw8[n * 32 + lane], acc);           // self term (pre-scaled)

    int cnt = g_degi[n];
    int beg = g_rowstart[n] - cnt;
    int j = 0;
    for (; j + 8 <= cnt; j += 8) {
        int s0 = g_csrc[beg + j],     s1 = g_csrc[beg + j + 1];
        int s2 = g_csrc[beg + j + 2], s3 = g_csrc[beg + j + 3];
        int s4 = g_csrc[beg + j + 4], s5 = g_csrc[beg + j + 5];
        int s6 = g_csrc[beg + j + 6], s7 = g_csrc[beg + j + 7];
        uint2 v0 = hw8[s0 * 32 + lane];
        uint2 v1 = hw8[s1 * 32 + lane];
        uint2 v2 = hw8[s2 * 32 + lane];
        uint2 v3 = hw8[s3 * 32 + lane];
        uint2 v4 = hw8[s4 * 32 + lane];
        uint2 v5 = hw8[s5 * 32 + lane];
        uint2 v6 = hw8[s6 * 32 + lane];
        uint2 v7 = hw8[s7 * 32 + lane];
        h4add(v0, acc); h4add(v1, acc); h4add(v2, acc); h4add(v3, acc);
        h4add(v4, acc); h4add(v5, acc); h4add(v6, acc); h4add(v7, acc);
    }
    for (; j < cnt; j++) {
        h4add(hw8[g_csrc[beg + j] * 32 + lane], acc);
    }
    float4 bv = ld4(&b[lane * 4]);
    acc.x = bv.x + acc.x * dn;
    acc.y = bv.y + acc.y * dn;
    acc.z = bv.z + acc.z * dn;
    acc.w = bv.w + acc.w * dn;
    return acc;
}

// ---------------- layer-1 aggregation: write g_agg (fp16) ----------------
__global__ void k_agg(const float* __restrict__ b) {
    int n = blockIdx.x * 8 + (threadIdx.x >> 5);
    int lane = threadIdx.x & 31;
    float4 acc = agg_node(n, lane, b);
    *(uint2*)&g_agg[n * DD + lane * 4] = f4toh4(acc);
}

// ---------------- layer-2 aggregation fused with relu + pooled scatter ----------------
__global__ void k_agg2pool(const float* __restrict__ b, const int* __restrict__ batch) {
    __shared__ float sacc[8][DD];
    __shared__ int   sg[8];
    int w = threadIdx.x >> 5;
    int n = blockIdx.x * 8 + w;
    int lane = threadIdx.x & 31;
    float4 acc = agg_node(n, lane, b);
    sacc[w][lane * 4 + 0] = fmaxf(acc.x, 0.f);
    sacc[w][lane * 4 + 1] = fmaxf(acc.y, 0.f);
    sacc[w][lane * 4 + 2] = fmaxf(acc.z, 0.f);
    sacc[w][lane * 4 + 3] = fmaxf(acc.w, 0.f);
    if (lane == 0) sg[w] = batch[n];
    __syncthreads();
    int d = threadIdx.x;
    if (d < DD) {
        float run = sacc[0][d];
        int cg = sg[0];
        #pragma unroll
        for (int k = 1; k < 8; k++) {
            int gk = sg[k];
            float vk = sacc[k][d];
            if (gk == cg) run += vk;
            else { atomicAdd(&g_pooled[cg * DD + d], run); cg = gk; run = vk; }
        }
        atomicAdd(&g_pooled[cg * DD + d], run);
    }
}

// ---------------- fp16 GEMM: hw = fp16( dinv[row] * (relu(agg) @ W) ) ----------------
// M=50048, N=128, K=128 in two K=64 chunks. 8 warps (4m x 2n), warp 32x64,
// m16n16k16 half frags, fp32 accum.
#define ASTRIDE 72    // halves
#define BSTRIDE 136   // halves
__global__ __launch_bounds__(256) void k_gemm(const float* __restrict__ W) {
    __shared__ __half As[128 * ASTRIDE];
    __shared__ __half Bs[64 * BSTRIDE];
    int m0 = blockIdx.x * 128;
    int tid = threadIdx.x;
    int wid = tid >> 5;
    int lane = tid & 31;
    int warp_m = wid >> 1;        // 0..3
    int warp_n = wid & 1;         // 0..1

    wmma::fragment<wmma::accumulator, 16, 16, 16, float> c[2][4];
    #pragma unroll
    for (int i = 0; i < 2; i++)
        #pragma unroll
        for (int j = 0; j < 4; j++) wmma::fill_fragment(c[i][j], 0.0f);

    const __half2 z2 = __float2half2_rn(0.f);
    for (int k0 = 0; k0 < DD; k0 += 64) {
        // A tile: 128 rows x 64 halves, relu at load (1024 uint4 loads)
        #pragma unroll
        for (int t = 0; t < 4; t++) {
            int f = tid + t * 256;
            int row = f >> 3, c8 = f & 7;
            uint4 v = *(const uint4*)&g_agg[(m0 + row) * DD + k0 + c8 * 8];
            __half2* h = (__half2*)&v;
            h[0] = __hmax2(h[0], z2); h[1] = __hmax2(h[1], z2);
            h[2] = __hmax2(h[2], z2); h[3] = __hmax2(h[3], z2);
            *(uint4*)&As[row * ASTRIDE + c8 * 8] = v;
        }
        // B tile: 64 k-rows x 128 cols, fp32 -> fp16 (2048 float4 loads)
        #pragma unroll
        for (int t = 0; t < 8; t++) {
            int f = tid + t * 256;
            int row = f >> 5, c4 = (f & 31) * 4;
            float4 v = ld4(&W[(k0 + row) * DD + c4]);
            *(uint2*)&Bs[row * BSTRIDE + c4] = f4toh4(v);
        }
        __syncthreads();
        #pragma unroll
        for (int kk = 0; kk < 4; kk++) {
            wmma::fragment<wmma::matrix_a, 16, 16, 16, __half, wmma::row_major> a[2];
            wmma::fragment<wmma::matrix_b, 16, 16, 16, __half, wmma::row_major> bfr[4];
            #pragma unroll
            for (int i = 0; i < 2; i++)
                wmma::load_matrix_sync(a[i], &As[(warp_m * 32 + i * 16) * ASTRIDE + kk * 16], ASTRIDE);
            #pragma unroll
            for (int j = 0; j < 4; j++)
                wmma::load_matrix_sync(bfr[j], &Bs[(kk * 16) * BSTRIDE + warp_n * 64 + j * 16], BSTRIDE);
            #pragma unroll
            for (int i = 0; i < 2; i++)
                #pragma unroll
                for (int j = 0; j < 4; j++)
                    wmma::mma_sync(c[i][j], a[i], bfr[j], c[i][j]);
        }
        __syncthreads();
    }

    // epilogue: stage frags in smem (reuse As as float), scale by dinv, fp16 stores
    float* stg = (float*)As + wid * 272;    // 272 floats per warp, 16B aligned
    int srow = lane >> 1;
    int scol = (lane & 1) * 8;
    #pragma unroll
    for (int i = 0; i < 2; i++) {
        #pragma unroll
        for (int j = 0; j < 4; j++) {
            wmma::store_matrix_sync(stg, c[i][j], 16, wmma::mem_row_major);
            __syncwarp();
            int grow = m0 + warp_m * 32 + i * 16 + srow;
            float dv = g_dinv[grow];
            float4 f0 = *(float4*)&stg[srow * 16 + scol];
            float4 f1 = *(float4*)&stg[srow * 16 + scol + 4];
            __half2 p0 = __floats2half2_rn(f0.x * dv, f0.y * dv);
            __half2 p1 = __floats2half2_rn(f0.z * dv, f0.w * dv);
            __half2 p2 = __floats2half2_rn(f1.x * dv, f1.y * dv);
            __half2 p3 = __floats2half2_rn(f1.z * dv, f1.w * dv);
            uint4 pk = make_uint4(*(unsigned*)&p0, *(unsigned*)&p1,
                                  *(unsigned*)&p2, *(unsigned*)&p3);
            *(uint4*)&g_hw[grow * DD + warp_n * 64 + j * 16 + scol] = pk;
            __syncwarp();
        }
    }
}

// ---------------- final: divide pooled by counts + FC ----------------
__global__ void k_fc(const float* __restrict__ fc_w, const float* __restrict__ fc_b,
                     float* __restrict__ out) {
    __shared__ float pm[DD];
    int g = blockIdx.x;
    int d = threadIdx.x;              // 128
    int cnt = g_gstart[g + 1] - g_gstart[g];
    float inv = 1.0f / fmaxf((float)cnt, 1.0f);
    pm[d] = g_pooled[g * DD + d] * inv;
    __syncthreads();
    if (d < NO) {
        float sum = fc_b[d];
        #pragma unroll 8
        for (int k = 0; k < DD; k++) sum += pm[k] * fc_w[k * NO + d];
        out[g * NO + d] = sum;
    }
}

// ---------------- launch ----------------
extern "C" void kernel_launch(void* const* d_in, const int* in_sizes, int n_in,
                              void* d_out, int out_size) {
    const int*   x     = (const int*)d_in[0];
    const int*   eidx  = (const int*)d_in[1];
    const int*   batch = (const int*)d_in[2];
    const float* embed = (const float*)d_in[3];
    const float* W0    = (const float*)d_in[4];
    const float* b0    = (const float*)d_in[5];
    const float* W1    = (const float*)d_in[6];
    const float* b1    = (const float*)d_in[7];
    const float* W2    = (const float*)d_in[8];
    const float* b2    = (const float*)d_in[9];
    const float* fc_w  = (const float*)d_in[10];
    const float* fc_b  = (const float*)d_in[11];
    float* out = (float*)d_out;

    const int* src = eidx;
    const int* dst = eidx + NE;

    void* p_degi;
    cudaGetSymbolAddress(&p_degi, g_degi);
    cudaMemsetAsync(p_degi, 0, NN * sizeof(int));

    // graph structure (boundaries + pooled zero fused into deg; t11 + xd into scan1)
    k_deg<<<(NE + 255) / 256, 256>>>(dst, batch);
    k_scan1<<<NCHUNK + NT, SCAN_BLK>>>(embed, W0, x);
    k_scan3<<<NCHUNK, SCAN_BLK>>>();
    k_fill<<<(NE + 255) / 256, 256>>>(src, dst);

    // layer 0: embed-gather fused into aggregation
    k_agg0<<<NN / 8, 256>>>(b0);

    // layer 1
    k_gemm<<<NNP / 128, 256>>>(W1);
    k_agg<<<NN / 8, 256>>>(b1);

    // layer 2 (aggregation fused with pooling)
    k_gemm<<<NNP / 128, 256>>>(W2);
    k_agg2pool<<<NN / 8, 256>>>(b2, batch);

    // fc
    k_fc<<<NG, DD>>>(fc_w, fc_b, out);
}